// round 3
// baseline (speedup 1.0000x reference)
#include <cuda_runtime.h>
#include <math.h>

// Problem constants (fixed by the dataset)
#define NN    50000
#define EE    800000
#define INC   256
#define HID   16
#define HEADS 8
#define C1    128          // HEADS*HID
#define OUTC  32
#define SLOPE 0.2f

// ---------------- scratch (device globals; no allocation allowed) ----------
__device__ __align__(16) float g_h1 [NN * C1];     // x @ W1
__device__ __align__(16) float g_h1o[NN * C1];     // layer-1 output (after relu)
__device__ __align__(16) float g_h2 [NN * OUTC];   // h1o @ W2
__device__ __align__(16) float g_als1[NN * HEADS];
__device__ __align__(16) float g_ald1[NN * HEADS];
__device__ __align__(16) float g_als2[NN];
__device__ __align__(16) float g_ald2[NN];
__device__ int   g_deg [NN];
__device__ int   g_cur [NN];
__device__ int   g_offs[NN + 1];
__device__ int   g_csr [EE];
__device__ int   g_bsums[128];

__device__ __forceinline__ float leaky(float x) { return x > 0.f ? x : SLOPE * x; }

// ---------------- CSR build --------------------------------------------------
__global__ void k_zero_counts() {
    int i = blockIdx.x * blockDim.x + threadIdx.x;
    if (i < NN) { g_deg[i] = 0; g_cur[i] = 0; }
}

__global__ void k_hist(const int* __restrict__ ei) {
    int e = blockIdx.x * blockDim.x + threadIdx.x;
    if (e < EE) {
        int d = ei[EE + e];
        atomicAdd(&g_deg[d], 1);
    }
}

// block-wise exclusive scan (chunk = 512)
__global__ void k_scan_block() {
    __shared__ int s[512];
    int t = threadIdx.x;
    int i = blockIdx.x * 512 + t;
    int v = (i < NN) ? g_deg[i] : 0;
    s[t] = v;
    __syncthreads();
    for (int off = 1; off < 512; off <<= 1) {
        int x = (t >= off) ? s[t - off] : 0;
        __syncthreads();
        s[t] += x;
        __syncthreads();
    }
    if (i < NN) g_offs[i] = s[t] - v;
    if (t == 511) g_bsums[blockIdx.x] = s[511];
}

__global__ void k_scan_bsums(int nb) {
    if (threadIdx.x == 0 && blockIdx.x == 0) {
        int run = 0;
        for (int b = 0; b < nb; b++) { int x = g_bsums[b]; g_bsums[b] = run; run += x; }
    }
}

__global__ void k_scan_add() {
    int i = blockIdx.x * blockDim.x + threadIdx.x;
    if (i < NN) g_offs[i] += g_bsums[i / 512];
    if (i == 0) g_offs[NN] = EE;
}

__global__ void k_scatter(const int* __restrict__ ei) {
    int e = blockIdx.x * blockDim.x + threadIdx.x;
    if (e < EE) {
        int s = ei[e];
        int d = ei[EE + e];
        int pos = g_offs[d] + atomicAdd(&g_cur[d], 1);
        g_csr[pos] = s;
    }
}

// ---------------- GEMM1: [NN,256] @ [256,128] -> g_h1 ------------------------
#define BM 64
#define BN 64
#define BK 16
__global__ void k_gemm1(const float* __restrict__ A, const float* __restrict__ B) {
    __shared__ float As[BK][BM];
    __shared__ float Bs[BK][BN];
    const int M = NN, K = INC, Nc = C1;
    int t  = threadIdx.x;
    int tx = t & 15, ty = t >> 4;
    int row0 = blockIdx.x * BM, col0 = blockIdx.y * BN;
    float acc[4][4] = {};
    for (int k0 = 0; k0 < K; k0 += BK) {
        #pragma unroll
        for (int i = 0; i < 4; i++) {
            int idx = t + i * 256;          // 1024 elems of A tile
            int m = idx >> 4, k = idx & 15;
            int gr = row0 + m;
            As[k][m] = (gr < M) ? A[gr * K + k0 + k] : 0.f;
        }
        #pragma unroll
        for (int i = 0; i < 4; i++) {
            int idx = t + i * 256;          // 1024 elems of B tile
            int k = idx >> 6, n = idx & 63;
            Bs[k][n] = B[(k0 + k) * Nc + col0 + n];
        }
        __syncthreads();
        #pragma unroll
        for (int k = 0; k < BK; k++) {
            float a[4], b[4];
            #pragma unroll
            for (int i = 0; i < 4; i++) a[i] = As[k][ty * 4 + i];
            #pragma unroll
            for (int j = 0; j < 4; j++) b[j] = Bs[k][tx * 4 + j];
            #pragma unroll
            for (int i = 0; i < 4; i++)
                #pragma unroll
                for (int j = 0; j < 4; j++)
                    acc[i][j] += a[i] * b[j];
        }
        __syncthreads();
    }
    #pragma unroll
    for (int i = 0; i < 4; i++) {
        int gr = row0 + ty * 4 + i;
        if (gr < M) {
            #pragma unroll
            for (int j = 0; j < 4; j++)
                g_h1[gr * Nc + col0 + tx * 4 + j] = acc[i][j];
        }
    }
}

// ---------------- per-node attention logits (layer 1) ------------------------
__global__ void k_al1(const float* __restrict__ a_s, const float* __restrict__ a_d) {
    int tid = blockIdx.x * blockDim.x + threadIdx.x;
    if (tid >= NN * HEADS) return;
    int n = tid >> 3, h = tid & 7;
    const float4* hv  = (const float4*)(g_h1 + n * C1 + h * HID);
    const float4* av  = (const float4*)(a_s + h * HID);
    const float4* dv  = (const float4*)(a_d + h * HID);
    float s = 0.f, d = 0.f;
    #pragma unroll
    for (int i = 0; i < 4; i++) {
        float4 v = hv[i], A = av[i], D = dv[i];
        s += v.x * A.x + v.y * A.y + v.z * A.z + v.w * A.w;
        d += v.x * D.x + v.y * D.y + v.z * D.z + v.w * D.w;
    }
    g_als1[tid] = s;
    g_ald1[tid] = d;
}

// ---------------- layer-1 aggregation: warp per dst node ---------------------
// lane l owns channels [4l, 4l+4)  (head = l>>2)
__global__ void k_agg1(const float* __restrict__ b1) {
    int w = (blockIdx.x * blockDim.x + threadIdx.x) >> 5;
    int lane = threadIdx.x & 31;
    if (w >= NN) return;
    int d = w;
    int h = lane >> 2;
    int beg = g_offs[d], cnt = g_deg[d];
    float ald = g_ald1[d * HEADS + h];

    // self-loop term
    float e_self = leaky(g_als1[d * HEADS + h] + ald);
    float m = e_self;
    for (int i = 0; i < cnt; i++) {
        int s = g_csr[beg + i];
        float e = leaky(g_als1[s * HEADS + h] + ald);
        m = fmaxf(m, e);
    }

    float denom = 0.f;
    float4 acc = make_float4(0.f, 0.f, 0.f, 0.f);
    const float4* h1v = (const float4*)g_h1;
    {
        float ex = __expf(e_self - m);
        denom += ex;
        float4 hv = h1v[d * 32 + lane];
        acc.x += hv.x * ex; acc.y += hv.y * ex; acc.z += hv.z * ex; acc.w += hv.w * ex;
    }
    for (int i = 0; i < cnt; i++) {
        int s = g_csr[beg + i];
        float e = leaky(g_als1[s * HEADS + h] + ald);
        float ex = __expf(e - m);
        denom += ex;
        float4 hv = h1v[s * 32 + lane];
        acc.x += hv.x * ex; acc.y += hv.y * ex; acc.z += hv.z * ex; acc.w += hv.w * ex;
    }
    float inv = 1.f / (denom + 1e-16f);
    float4 bb = ((const float4*)b1)[lane];
    float4 o;
    o.x = fmaxf(acc.x * inv + bb.x, 0.f);
    o.y = fmaxf(acc.y * inv + bb.y, 0.f);
    o.z = fmaxf(acc.z * inv + bb.z, 0.f);
    o.w = fmaxf(acc.w * inv + bb.w, 0.f);
    ((float4*)g_h1o)[d * 32 + lane] = o;
}

// ---------------- GEMM2: [NN,128] @ [128,32] -> g_h2 -------------------------
__global__ void k_gemm2(const float* __restrict__ W) {
    __shared__ float Ws[C1 * OUTC];
    int t = threadIdx.x;           // 256 threads
    for (int i = t; i < C1 * OUTC; i += 256) Ws[i] = W[i];
    __syncthreads();
    int col = t & 31, r = t >> 5;  // 8 rows in flight
    int row0 = blockIdx.x * 64;
    for (int rr = r; rr < 64; rr += 8) {
        int row = row0 + rr;
        if (row >= NN) break;
        const float4* a = (const float4*)(g_h1o + row * C1);
        float acc = 0.f;
        #pragma unroll
        for (int k4 = 0; k4 < 32; k4++) {
            float4 av = a[k4];
            acc += av.x * Ws[(k4 * 4 + 0) * 32 + col];
            acc += av.y * Ws[(k4 * 4 + 1) * 32 + col];
            acc += av.z * Ws[(k4 * 4 + 2) * 32 + col];
            acc += av.w * Ws[(k4 * 4 + 3) * 32 + col];
        }
        g_h2[row * 32 + col] = acc;
    }
}

// ---------------- per-node attention logits (layer 2, 1 head) ----------------
__global__ void k_al2(const float* __restrict__ a_s, const float* __restrict__ a_d) {
    int n = blockIdx.x * blockDim.x + threadIdx.x;
    if (n >= NN) return;
    const float4* hv = (const float4*)(g_h2 + n * OUTC);
    const float4* av = (const float4*)a_s;
    const float4* dv = (const float4*)a_d;
    float s = 0.f, d = 0.f;
    #pragma unroll
    for (int i = 0; i < 8; i++) {
        float4 v = hv[i], A = av[i], D = dv[i];
        s += v.x * A.x + v.y * A.y + v.z * A.z + v.w * A.w;
        d += v.x * D.x + v.y * D.y + v.z * D.z + v.w * D.w;
    }
    g_als2[n] = s;
    g_ald2[n] = d;
}

// ---------------- layer-2 aggregation + log_softmax: warp per dst ------------
__global__ void k_agg2(const float* __restrict__ b2, float* __restrict__ out) {
    int w = (blockIdx.x * blockDim.x + threadIdx.x) >> 5;
    int lane = threadIdx.x & 31;
    if (w >= NN) return;
    int d = w;
    int beg = g_offs[d], cnt = g_deg[d];
    float ald = g_ald2[d];

    float e_self = leaky(g_als2[d] + ald);
    // pass 1: max over edges (parallel across lanes)
    float m = e_self;
    for (int i = lane; i < cnt; i += 32) {
        int s = g_csr[beg + i];
        m = fmaxf(m, leaky(g_als2[s] + ald));
    }
    #pragma unroll
    for (int off = 16; off > 0; off >>= 1)
        m = fmaxf(m, __shfl_xor_sync(0xFFFFFFFF, m, off));

    // pass 2: serial over edges, lane owns one output channel
    float denom = 0.f, acc = 0.f;
    {
        float ex = __expf(e_self - m);
        denom += ex;
        acc += g_h2[d * 32 + lane] * ex;
    }
    for (int i = 0; i < cnt; i++) {
        int s = g_csr[beg + i];
        float e = leaky(g_als2[s] + ald);
        float ex = __expf(e - m);
        denom += ex;
        acc += g_h2[s * 32 + lane] * ex;
    }
    float r = acc / (denom + 1e-16f) + b2[lane];

    // log_softmax over the 32 lanes
    float mx = r;
    #pragma unroll
    for (int off = 16; off > 0; off >>= 1)
        mx = fmaxf(mx, __shfl_xor_sync(0xFFFFFFFF, mx, off));
    float ee = expf(r - mx);
    float ssum = ee;
    #pragma unroll
    for (int off = 16; off > 0; off >>= 1)
        ssum += __shfl_xor_sync(0xFFFFFFFF, ssum, off);
    out[d * 32 + lane] = r - mx - logf(ssum);
}

// ---------------- launch ------------------------------------------------------
extern "C" void kernel_launch(void* const* d_in, const int* in_sizes, int n_in,
                              void* d_out, int out_size) {
    const float* x      = (const float*)d_in[0];
    const int*   ei     = (const int*)d_in[1];     // JAX x64 disabled -> int32
    const float* W1     = (const float*)d_in[2];
    const float* a_src1 = (const float*)d_in[3];
    const float* a_dst1 = (const float*)d_in[4];
    const float* b1     = (const float*)d_in[5];
    const float* W2     = (const float*)d_in[6];
    const float* a_src2 = (const float*)d_in[7];
    const float* a_dst2 = (const float*)d_in[8];
    const float* b2     = (const float*)d_in[9];
    float*       out    = (float*)d_out;

    const int nbScan = (NN + 511) / 512;   // 98

    // CSR build
    k_zero_counts<<<(NN + 255) / 256, 256>>>();
    k_hist<<<(EE + 255) / 256, 256>>>(ei);
    k_scan_block<<<nbScan, 512>>>();
    k_scan_bsums<<<1, 32>>>(nbScan);
    k_scan_add<<<(NN + 255) / 256, 256>>>();
    k_scatter<<<(EE + 255) / 256, 256>>>(ei);

    // layer 1
    dim3 g1((NN + BM - 1) / BM, C1 / BN);
    k_gemm1<<<g1, 256>>>(x, W1);
    k_al1<<<(NN * HEADS + 255) / 256, 256>>>(a_src1, a_dst1);
    k_agg1<<<(NN * 32 + 255) / 256, 256>>>(b1);

    // layer 2
    k_gemm2<<<(NN + 63) / 64, 256>>>(W2);
    k_al2<<<(NN + 255) / 256, 256>>>(a_src2, a_dst2);
    k_agg2<<<(NN * 32 + 255) / 256, 256>>>(b2, out);
}

// round 4
// speedup vs baseline: 1.0068x; 1.0068x over previous
#include <cuda_runtime.h>
#include <math.h>

// Problem constants (fixed by the dataset)
#define NN    50000
#define EE    800000
#define INC   256
#define HID   16
#define HEADS 8
#define C1    128          // HEADS*HID
#define OUTC  32
#define SLOPE 0.2f

// ---------------- scratch (device globals; no allocation allowed) ----------
__device__ __align__(16) float g_h1 [NN * C1];     // x @ W1
__device__ __align__(16) float g_h1o[NN * C1];     // layer-1 output (after relu)
__device__ __align__(16) float g_h2 [NN * OUTC];   // h1o @ W2
__device__ __align__(16) float g_als1[NN * HEADS];
__device__ __align__(16) float g_ald1[NN * HEADS];
__device__ __align__(16) float g_als2[NN];
__device__ __align__(16) float g_ald2[NN];
__device__ int   g_deg [NN];
__device__ int   g_cur [NN];
__device__ int   g_offs[NN + 1];
__device__ int   g_csr [EE];
__device__ int   g_bsums[128];

__device__ __forceinline__ float leaky(float x) { return x > 0.f ? x : SLOPE * x; }

// ---------------- CSR build --------------------------------------------------
__global__ void k_zero_counts() {
    int i = blockIdx.x * blockDim.x + threadIdx.x;
    if (i < NN) { g_deg[i] = 0; g_cur[i] = 0; }
}

__global__ void k_hist(const int* __restrict__ ei) {
    int e = blockIdx.x * blockDim.x + threadIdx.x;
    if (e < EE) {
        int d = ei[EE + e];
        atomicAdd(&g_deg[d], 1);
    }
}

// block-wise exclusive scan (chunk = 512)
__global__ void k_scan_block() {
    __shared__ int s[512];
    int t = threadIdx.x;
    int i = blockIdx.x * 512 + t;
    int v = (i < NN) ? g_deg[i] : 0;
    s[t] = v;
    __syncthreads();
    for (int off = 1; off < 512; off <<= 1) {
        int x = (t >= off) ? s[t - off] : 0;
        __syncthreads();
        s[t] += x;
        __syncthreads();
    }
    if (i < NN) g_offs[i] = s[t] - v;
    if (t == 511) g_bsums[blockIdx.x] = s[511];
}

__global__ void k_scan_bsums(int nb) {
    if (threadIdx.x == 0 && blockIdx.x == 0) {
        int run = 0;
        for (int b = 0; b < nb; b++) { int x = g_bsums[b]; g_bsums[b] = run; run += x; }
    }
}

__global__ void k_scan_add() {
    int i = blockIdx.x * blockDim.x + threadIdx.x;
    if (i < NN) g_offs[i] += g_bsums[i / 512];
    if (i == 0) g_offs[NN] = EE;
}

__global__ void k_scatter(const int* __restrict__ ei) {
    int e = blockIdx.x * blockDim.x + threadIdx.x;
    if (e < EE) {
        int s = ei[e];
        int d = ei[EE + e];
        int pos = g_offs[d] + atomicAdd(&g_cur[d], 1);
        g_csr[pos] = s;
    }
}

// ---------------- GEMM1: [NN,256] @ [256,128] -> g_h1 ------------------------
#define BM 64
#define BN 64
#define BK 16
__global__ void k_gemm1(const float* __restrict__ A, const float* __restrict__ B) {
    __shared__ float As[BK][BM];
    __shared__ float Bs[BK][BN];
    const int M = NN, K = INC, Nc = C1;
    int t  = threadIdx.x;
    int tx = t & 15, ty = t >> 4;
    int row0 = blockIdx.x * BM, col0 = blockIdx.y * BN;
    float acc[4][4] = {};
    for (int k0 = 0; k0 < K; k0 += BK) {
        #pragma unroll
        for (int i = 0; i < 4; i++) {
            int idx = t + i * 256;          // 1024 elems of A tile
            int m = idx >> 4, k = idx & 15;
            int gr = row0 + m;
            As[k][m] = (gr < M) ? A[gr * K + k0 + k] : 0.f;
        }
        #pragma unroll
        for (int i = 0; i < 4; i++) {
            int idx = t + i * 256;          // 1024 elems of B tile
            int k = idx >> 6, n = idx & 63;
            Bs[k][n] = B[(k0 + k) * Nc + col0 + n];
        }
        __syncthreads();
        #pragma unroll
        for (int k = 0; k < BK; k++) {
            float a[4], b[4];
            #pragma unroll
            for (int i = 0; i < 4; i++) a[i] = As[k][ty * 4 + i];
            #pragma unroll
            for (int j = 0; j < 4; j++) b[j] = Bs[k][tx * 4 + j];
            #pragma unroll
            for (int i = 0; i < 4; i++)
                #pragma unroll
                for (int j = 0; j < 4; j++)
                    acc[i][j] += a[i] * b[j];
        }
        __syncthreads();
    }
    #pragma unroll
    for (int i = 0; i < 4; i++) {
        int gr = row0 + ty * 4 + i;
        if (gr < M) {
            #pragma unroll
            for (int j = 0; j < 4; j++)
                g_h1[gr * Nc + col0 + tx * 4 + j] = acc[i][j];
        }
    }
}

// ---------------- per-node attention logits (layer 1) ------------------------
__global__ void k_al1(const float* __restrict__ a_s, const float* __restrict__ a_d) {
    int tid = blockIdx.x * blockDim.x + threadIdx.x;
    if (tid >= NN * HEADS) return;
    int n = tid >> 3, h = tid & 7;
    const float4* hv  = (const float4*)(g_h1 + n * C1 + h * HID);
    const float4* av  = (const float4*)(a_s + h * HID);
    const float4* dv  = (const float4*)(a_d + h * HID);
    float s = 0.f, d = 0.f;
    #pragma unroll
    for (int i = 0; i < 4; i++) {
        float4 v = hv[i], A = av[i], D = dv[i];
        s += v.x * A.x + v.y * A.y + v.z * A.z + v.w * A.w;
        d += v.x * D.x + v.y * D.y + v.z * D.z + v.w * D.w;
    }
    g_als1[tid] = s;
    g_ald1[tid] = d;
}

// ---------------- layer-1 aggregation: warp per dst node ---------------------
// lane l owns channels [4l, 4l+4)  (head = l>>2)
__global__ void k_agg1(const float* __restrict__ b1) {
    int w = (blockIdx.x * blockDim.x + threadIdx.x) >> 5;
    int lane = threadIdx.x & 31;
    if (w >= NN) return;
    int d = w;
    int h = lane >> 2;
    int beg = g_offs[d], cnt = g_deg[d];
    float ald = g_ald1[d * HEADS + h];

    // self-loop term
    float e_self = leaky(g_als1[d * HEADS + h] + ald);
    float m = e_self;
    for (int i = 0; i < cnt; i++) {
        int s = g_csr[beg + i];
        float e = leaky(g_als1[s * HEADS + h] + ald);
        m = fmaxf(m, e);
    }

    float denom = 0.f;
    float4 acc = make_float4(0.f, 0.f, 0.f, 0.f);
    const float4* h1v = (const float4*)g_h1;
    {
        float ex = __expf(e_self - m);
        denom += ex;
        float4 hv = h1v[d * 32 + lane];
        acc.x += hv.x * ex; acc.y += hv.y * ex; acc.z += hv.z * ex; acc.w += hv.w * ex;
    }
    for (int i = 0; i < cnt; i++) {
        int s = g_csr[beg + i];
        float e = leaky(g_als1[s * HEADS + h] + ald);
        float ex = __expf(e - m);
        denom += ex;
        float4 hv = h1v[s * 32 + lane];
        acc.x += hv.x * ex; acc.y += hv.y * ex; acc.z += hv.z * ex; acc.w += hv.w * ex;
    }
    float inv = 1.f / (denom + 1e-16f);
    float4 bb = ((const float4*)b1)[lane];
    float4 o;
    o.x = fmaxf(acc.x * inv + bb.x, 0.f);
    o.y = fmaxf(acc.y * inv + bb.y, 0.f);
    o.z = fmaxf(acc.z * inv + bb.z, 0.f);
    o.w = fmaxf(acc.w * inv + bb.w, 0.f);
    ((float4*)g_h1o)[d * 32 + lane] = o;
}

// ---------------- GEMM2: [NN,128] @ [128,32] -> g_h2 -------------------------
__global__ void k_gemm2(const float* __restrict__ W) {
    __shared__ float Ws[C1 * OUTC];
    int t = threadIdx.x;           // 256 threads
    for (int i = t; i < C1 * OUTC; i += 256) Ws[i] = W[i];
    __syncthreads();
    int col = t & 31, r = t >> 5;  // 8 rows in flight
    int row0 = blockIdx.x * 64;
    for (int rr = r; rr < 64; rr += 8) {
        int row = row0 + rr;
        if (row >= NN) break;
        const float4* a = (const float4*)(g_h1o + row * C1);
        float acc = 0.f;
        #pragma unroll
        for (int k4 = 0; k4 < 32; k4++) {
            float4 av = a[k4];
            acc += av.x * Ws[(k4 * 4 + 0) * 32 + col];
            acc += av.y * Ws[(k4 * 4 + 1) * 32 + col];
            acc += av.z * Ws[(k4 * 4 + 2) * 32 + col];
            acc += av.w * Ws[(k4 * 4 + 3) * 32 + col];
        }
        g_h2[row * 32 + col] = acc;
    }
}

// ---------------- per-node attention logits (layer 2, 1 head) ----------------
__global__ void k_al2(const float* __restrict__ a_s, const float* __restrict__ a_d) {
    int n = blockIdx.x * blockDim.x + threadIdx.x;
    if (n >= NN) return;
    const float4* hv = (const float4*)(g_h2 + n * OUTC);
    const float4* av = (const float4*)a_s;
    const float4* dv = (const float4*)a_d;
    float s = 0.f, d = 0.f;
    #pragma unroll
    for (int i = 0; i < 8; i++) {
        float4 v = hv[i], A = av[i], D = dv[i];
        s += v.x * A.x + v.y * A.y + v.z * A.z + v.w * A.w;
        d += v.x * D.x + v.y * D.y + v.z * D.z + v.w * D.w;
    }
    g_als2[n] = s;
    g_ald2[n] = d;
}

// ---------------- layer-2 aggregation + log_softmax: warp per dst ------------
__global__ void k_agg2(const float* __restrict__ b2, float* __restrict__ out) {
    int w = (blockIdx.x * blockDim.x + threadIdx.x) >> 5;
    int lane = threadIdx.x & 31;
    if (w >= NN) return;
    int d = w;
    int beg = g_offs[d], cnt = g_deg[d];
    float ald = g_ald2[d];

    float e_self = leaky(g_als2[d] + ald);
    // pass 1: max over edges (parallel across lanes)
    float m = e_self;
    for (int i = lane; i < cnt; i += 32) {
        int s = g_csr[beg + i];
        m = fmaxf(m, leaky(g_als2[s] + ald));
    }
    #pragma unroll
    for (int off = 16; off > 0; off >>= 1)
        m = fmaxf(m, __shfl_xor_sync(0xFFFFFFFF, m, off));

    // pass 2: serial over edges, lane owns one output channel
    float denom = 0.f, acc = 0.f;
    {
        float ex = __expf(e_self - m);
        denom += ex;
        acc += g_h2[d * 32 + lane] * ex;
    }
    for (int i = 0; i < cnt; i++) {
        int s = g_csr[beg + i];
        float e = leaky(g_als2[s] + ald);
        float ex = __expf(e - m);
        denom += ex;
        acc += g_h2[s * 32 + lane] * ex;
    }
    float r = acc / (denom + 1e-16f) + b2[lane];

    // log_softmax over the 32 lanes
    float mx = r;
    #pragma unroll
    for (int off = 16; off > 0; off >>= 1)
        mx = fmaxf(mx, __shfl_xor_sync(0xFFFFFFFF, mx, off));
    float ee = expf(r - mx);
    float ssum = ee;
    #pragma unroll
    for (int off = 16; off > 0; off >>= 1)
        ssum += __shfl_xor_sync(0xFFFFFFFF, ssum, off);
    out[d * 32 + lane] = r - mx - logf(ssum);
}

// ---------------- launch ------------------------------------------------------
extern "C" void kernel_launch(void* const* d_in, const int* in_sizes, int n_in,
                              void* d_out, int out_size) {
    const float* x      = (const float*)d_in[0];
    const int*   ei     = (const int*)d_in[1];     // JAX x64 disabled -> int32
    const float* W1     = (const float*)d_in[2];
    const float* a_src1 = (const float*)d_in[3];
    const float* a_dst1 = (const float*)d_in[4];
    const float* b1     = (const float*)d_in[5];
    const float* W2     = (const float*)d_in[6];
    const float* a_src2 = (const float*)d_in[7];
    const float* a_dst2 = (const float*)d_in[8];
    const float* b2     = (const float*)d_in[9];
    float*       out    = (float*)d_out;

    const int nbScan = (NN + 511) / 512;   // 98

    // CSR build
    k_zero_counts<<<(NN + 255) / 256, 256>>>();
    k_hist<<<(EE + 255) / 256, 256>>>(ei);
    k_scan_block<<<nbScan, 512>>>();
    k_scan_bsums<<<1, 32>>>(nbScan);
    k_scan_add<<<(NN + 255) / 256, 256>>>();
    k_scatter<<<(EE + 255) / 256, 256>>>(ei);

    // layer 1
    dim3 g1((NN + BM - 1) / BM, C1 / BN);
    k_gemm1<<<g1, 256>>>(x, W1);
    k_al1<<<(NN * HEADS + 255) / 256, 256>>>(a_src1, a_dst1);
    k_agg1<<<(NN * 32 + 255) / 256, 256>>>(b1);

    // layer 2
    k_gemm2<<<(NN + 63) / 64, 256>>>(W2);
    k_al2<<<(NN + 255) / 256, 256>>>(a_src2, a_dst2);
    k_agg2<<<(NN * 32 + 255) / 256, 256>>>(b2, out);
}